// round 7
// baseline (speedup 1.0000x reference)
#include <cuda_runtime.h>
#include <cstdint>
#include <cstddef>

// Problem constants (fixed by the dataset): B=4, S=4096, D=256, fp32.
#define S_LEN    4096
#define HD       256
#define BM       64            // queries per CTA
#define BN       64            // keys per tile
#define NT       (S_LEN / BN)  // 64 key tiles
#define NTHREADS 256
#define LDK      260           // padded K smem stride (floats): row bank shift 4
#define LDP      68            // padded P smem stride (floats)
#define SCALE    0.0625f       // 1/sqrt(256)

// smem layout (floats): Qs[BM*HD] Ks[BN*LDK] Vs[BN*HD] Ps[BM*LDP] rowm[BM] rowl[BM] rowc[BM]
#define SMEM_FLOATS (BM*HD + BN*LDK + BN*HD + BM*LDP + 3*BM)
#define SMEM_BYTES  (SMEM_FLOATS * 4)

typedef unsigned long long u64;

// ---- packed fp32x2 math (Blackwell FFMA2 path; only reachable via PTX) ----
__device__ __forceinline__ u64 fma2(u64 a, u64 b, u64 c) {
    u64 d;
    asm("fma.rn.f32x2 %0, %1, %2, %3;" : "=l"(d) : "l"(a), "l"(b), "l"(c));
    return d;
}
__device__ __forceinline__ u64 mul2(u64 a, u64 b) {
    u64 d;
    asm("mul.rn.f32x2 %0, %1, %2;" : "=l"(d) : "l"(a), "l"(b));
    return d;
}
__device__ __forceinline__ u64 pack2(float x, float y) {
    u64 r;
    asm("mov.b64 %0, {%1, %2};" : "=l"(r) : "f"(x), "f"(y));
    return r;
}
__device__ __forceinline__ float2 unpack2(u64 v) {
    float2 f;
    asm("mov.b64 {%0, %1}, %2;" : "=f"(f.x), "=f"(f.y) : "l"(v));
    return f;
}

// ---- cp.async helpers ----
__device__ __forceinline__ void cpa16(uint32_t saddr, const void* gptr) {
    asm volatile("cp.async.cg.shared.global [%0], [%1], 16;" :: "r"(saddr), "l"(gptr) : "memory");
}
__device__ __forceinline__ void cpa_commit() {
    asm volatile("cp.async.commit_group;" ::: "memory");
}
__device__ __forceinline__ void cpa_wait_all() {
    asm volatile("cp.async.wait_group 0;" ::: "memory");
}

__global__ void __launch_bounds__(NTHREADS, 1)
attn_flash_f32x2(const float* __restrict__ q,
                 const float* __restrict__ k,
                 const float* __restrict__ v,
                 float* __restrict__ out)
{
    extern __shared__ float smem[];
    float* Qs   = smem;               // [BM][HD], pre-scaled by 1/sqrt(D)
    float* Ks   = Qs + BM*HD;         // [BN][LDK]
    float* Vs   = Ks + BN*LDK;        // [BN][HD]
    float* Ps   = Vs + BN*HD;         // [BM][LDP] scores / probabilities
    float* rowm = Ps + BM*LDP;        // running max
    float* rowl = rowm + BM;          // running denom
    float* rowc = rowl + BM;          // per-tile correction factor

    const int tid = threadIdx.x;
    const int b   = blockIdx.y;
    const int q0  = blockIdx.x * BM;
    const int tx  = tid & 15;         // 16 groups: k-cols (QK) / d-cols (PV)
    const int ty  = tid >> 4;         // 16 groups: 4 q-rows each

    const float* gQ = q + ((size_t)b * S_LEN + q0) * HD;
    const float* gK = k + (size_t)b * S_LEN * HD;
    const float* gV = v + (size_t)b * S_LEN * HD;

    const uint32_t sKs = (uint32_t)__cvta_generic_to_shared(Ks);
    const uint32_t sVs = (uint32_t)__cvta_generic_to_shared(Vs);

    // ---- prologue: load Q (scaled), async-load K(0)/V(0), init stats ----
    #pragma unroll
    for (int it = 0; it < (BM*HD/4)/NTHREADS; ++it) {
        int idx = it * NTHREADS + tid;
        int r = idx >> 6;               // HD/4 = 64 float4 per row
        int c = (idx & 63) << 2;
        float4 val = *(const float4*)(gQ + (size_t)r * HD + c);
        val.x *= SCALE; val.y *= SCALE; val.z *= SCALE; val.w *= SCALE;
        *(float4*)(Qs + r * HD + c) = val;
    }
    for (int idx = tid; idx < BN*(HD/4); idx += NTHREADS) {
        int r = idx >> 6, c = (idx & 63) << 2;
        cpa16(sKs + (uint32_t)(r * LDK + c) * 4u, gK + (size_t)r * HD + c);
    }
    cpa_commit();
    for (int idx = tid; idx < BN*(HD/4); idx += NTHREADS) {
        cpa16(sVs + (uint32_t)idx * 16u, gV + (size_t)idx * 4);
    }
    cpa_commit();
    if (tid < BM) { rowm[tid] = -1e30f; rowl[tid] = 0.0f; }

    // output accumulators: 4 q-rows x 8 d-pairs (d = 64*j4 + 4*tx + {0..3})
    u64 o2[4][8];
    #pragma unroll
    for (int i = 0; i < 4; ++i)
        #pragma unroll
        for (int j = 0; j < 8; ++j) o2[i][j] = 0ULL;

    const float* qbase = Qs + (ty * 4) * HD;

    for (int t = 0; t < NT; ++t) {
        cpa_wait_all();
        __syncthreads();                      // K(t), V(t) visible to all

        // ---------- phase 1: S = (Q*scale) @ K^T, 4x4 per thread ----------
        // thread's k-rows: tx + 16*j (consecutive lanes -> conflict deg 2)
        u64 acc[4][4];
        #pragma unroll
        for (int i = 0; i < 4; ++i)
            #pragma unroll
            for (int j = 0; j < 4; ++j) acc[i][j] = 0ULL;

        #pragma unroll 2
        for (int kk = 0; kk < HD; kk += 4) {
            ulonglong2 a[4], bb[4];
            #pragma unroll
            for (int i = 0; i < 4; ++i)
                a[i] = *(const ulonglong2*)(qbase + i * HD + kk);
            #pragma unroll
            for (int j = 0; j < 4; ++j)
                bb[j] = *(const ulonglong2*)(Ks + (tx + 16 * j) * LDK + kk);
            #pragma unroll
            for (int i = 0; i < 4; ++i)
                #pragma unroll
                for (int j = 0; j < 4; ++j) {
                    acc[i][j] = fma2(a[i].x, bb[j].x, acc[i][j]);
                    acc[i][j] = fma2(a[i].y, bb[j].y, acc[i][j]);
                }
        }
        #pragma unroll
        for (int i = 0; i < 4; ++i)
            #pragma unroll
            for (int j = 0; j < 4; ++j) {
                float2 f = unpack2(acc[i][j]);
                Ps[(ty * 4 + i) * LDP + tx + 16 * j] = f.x + f.y;
            }
        __syncthreads();                      // Ps complete; Ks now free

        // prefetch K(t+1) into the freed K buffer (overlaps softmax + PV)
        if (t + 1 < NT) {
            const float* srcK = gK + (size_t)(t + 1) * BN * HD;
            for (int idx = tid; idx < BN*(HD/4); idx += NTHREADS) {
                int r = idx >> 6, c = (idx & 63) << 2;
                cpa16(sKs + (uint32_t)(r * LDK + c) * 4u, srcK + (size_t)r * HD + c);
            }
        }
        cpa_commit();

        // ---------- phase 2: online softmax, 4 lanes per row ----------
        {
            int row = tid >> 2;
            int sub = tid & 3;
            float* prow = Ps + row * LDP + sub * 16;
            float4 x0 = *(float4*)(prow + 0);
            float4 x1 = *(float4*)(prow + 4);
            float4 x2 = *(float4*)(prow + 8);
            float4 x3 = *(float4*)(prow + 12);

            float mloc = fmaxf(fmaxf(fmaxf(x0.x, x0.y), fmaxf(x0.z, x0.w)),
                               fmaxf(fmaxf(x1.x, x1.y), fmaxf(x1.z, x1.w)));
            mloc = fmaxf(mloc, fmaxf(fmaxf(fmaxf(x2.x, x2.y), fmaxf(x2.z, x2.w)),
                                     fmaxf(fmaxf(x3.x, x3.y), fmaxf(x3.z, x3.w))));
            mloc = fmaxf(mloc, __shfl_xor_sync(0xffffffffu, mloc, 1));
            mloc = fmaxf(mloc, __shfl_xor_sync(0xffffffffu, mloc, 2));

            float mold = rowm[row];
            float mnew = fmaxf(mold, mloc);

            x0.x = __expf(x0.x - mnew); x0.y = __expf(x0.y - mnew);
            x0.z = __expf(x0.z - mnew); x0.w = __expf(x0.w - mnew);
            x1.x = __expf(x1.x - mnew); x1.y = __expf(x1.y - mnew);
            x1.z = __expf(x1.z - mnew); x1.w = __expf(x1.w - mnew);
            x2.x = __expf(x2.x - mnew); x2.y = __expf(x2.y - mnew);
            x2.z = __expf(x2.z - mnew); x2.w = __expf(x2.w - mnew);
            x3.x = __expf(x3.x - mnew); x3.y = __expf(x3.y - mnew);
            x3.z = __expf(x3.z - mnew); x3.w = __expf(x3.w - mnew);

            float ssum = (x0.x + x0.y + x0.z + x0.w) + (x1.x + x1.y + x1.z + x1.w)
                       + (x2.x + x2.y + x2.z + x2.w) + (x3.x + x3.y + x3.z + x3.w);

            *(float4*)(prow + 0)  = x0;
            *(float4*)(prow + 4)  = x1;
            *(float4*)(prow + 8)  = x2;
            *(float4*)(prow + 12) = x3;

            ssum += __shfl_xor_sync(0xffffffffu, ssum, 1);
            ssum += __shfl_xor_sync(0xffffffffu, ssum, 2);

            if (sub == 0) {
                float corr = __expf(mold - mnew);   // exp(-1e30-..) -> 0 on first tile
                rowc[row] = corr;
                rowm[row] = mnew;
                rowl[row] = rowl[row] * corr + ssum;
            }
        }
        __syncthreads();                      // P, rowc stable

        // ---------- phase 3: O = O*corr + P @ V ----------
        {
            u64 cc[4];
            #pragma unroll
            for (int i = 0; i < 4; ++i) {
                float c = rowc[ty * 4 + i];
                cc[i] = pack2(c, c);
            }
            #pragma unroll
            for (int i = 0; i < 4; ++i)
                #pragma unroll
                for (int j = 0; j < 8; ++j) o2[i][j] = mul2(o2[i][j], cc[i]);

            #pragma unroll 2
            for (int kk = 0; kk < BN; ++kk) {
                u64 pp[4];
                #pragma unroll
                for (int i = 0; i < 4; ++i) {
                    float p = Ps[(ty * 4 + i) * LDP + kk];   // warp-broadcast
                    pp[i] = pack2(p, p);
                }
                #pragma unroll
                for (int j4 = 0; j4 < 4; ++j4) {
                    // lanes 0..15 cover 64 consecutive floats -> conflict-free
                    ulonglong2 vv = *(const ulonglong2*)(Vs + kk * HD + j4 * 64 + tx * 4);
                    #pragma unroll
                    for (int i = 0; i < 4; ++i) {
                        o2[i][2 * j4]     = fma2(pp[i], vv.x, o2[i][2 * j4]);
                        o2[i][2 * j4 + 1] = fma2(pp[i], vv.y, o2[i][2 * j4 + 1]);
                    }
                }
            }
        }
        __syncthreads();                      // Vs now free

        // prefetch V(t+1)
        if (t + 1 < NT) {
            const float* srcV = gV + (size_t)(t + 1) * BN * HD;
            for (int idx = tid; idx < BN*(HD/4); idx += NTHREADS)
                cpa16(sVs + (uint32_t)idx * 16u, srcV + (size_t)idx * 4);
        }
        cpa_commit();
    }

    // ---- epilogue: normalize by running denom, store ----
    #pragma unroll
    for (int i = 0; i < 4; ++i) {
        int qr = ty * 4 + i;
        float inv = __fdividef(1.0f, rowl[qr]);
        float* dst = out + ((size_t)b * S_LEN + (q0 + qr)) * HD + tx * 4;
        #pragma unroll
        for (int j4 = 0; j4 < 4; ++j4) {
            float2 lo = unpack2(o2[i][2 * j4]);
            float2 hi = unpack2(o2[i][2 * j4 + 1]);
            float4 val = make_float4(lo.x * inv, lo.y * inv, hi.x * inv, hi.y * inv);
            *(float4*)(dst + j4 * 64) = val;
        }
    }
}

extern "C" void kernel_launch(void* const* d_in, const int* in_sizes, int n_in,
                              void* d_out, int out_size) {
    const float* q = (const float*)d_in[0];
    const float* k = (const float*)d_in[1];
    const float* v = (const float*)d_in[2];
    float* out = (float*)d_out;

    const int B = in_sizes[0] / (S_LEN * HD);

    cudaFuncSetAttribute(attn_flash_f32x2,
                         cudaFuncAttributeMaxDynamicSharedMemorySize, SMEM_BYTES);

    dim3 grid(S_LEN / BM, B);
    attn_flash_f32x2<<<grid, NTHREADS, SMEM_BYTES>>>(q, k, v, out);
}

// round 8
// speedup vs baseline: 4.2761x; 4.2761x over previous
#include <cuda_runtime.h>
#include <cstdint>
#include <cstddef>

// Problem constants (fixed by the dataset): B=4, S=4096, D=256, fp32.
#define S_LEN    4096
#define HD       256
#define BM       64            // queries per CTA
#define BN       64            // keys per tile
#define NT       (S_LEN / BN)  // 64 key tiles
#define NTHREADS 256
#define LDQ      260           // padded Q smem stride -> conflict-free A-frag LDS
#define LDK      260           // padded K smem stride -> conflict-free B-frag LDS
#define LDV      264           // padded V smem stride -> conflict-free B-frag LDS
#define LDP      68            // padded P smem stride
#define SCALE    0.0625f       // 1/sqrt(256)

// smem floats: Qs[BM*LDQ] Ks[BN*LDK] Vs[BN*LDV] Ps[BM*LDP] rowm[BM] rowl[BM] rowc[BM]
#define SMEM_FLOATS (BM*LDQ + BN*LDK + BN*LDV + BM*LDP + 3*BM)
#define SMEM_BYTES  (SMEM_FLOATS * 4)

// ---- tf32 helpers ----
__device__ __forceinline__ uint32_t f2tf(float x) {
    uint32_t r;
    asm("cvt.rna.tf32.f32 %0, %1;" : "=r"(r) : "f"(x));
    return r;
}

// mma.sync m16n8k8 row.col tf32, D == C accumulate in place
__device__ __forceinline__ void mma_tf32(float& d0, float& d1, float& d2, float& d3,
                                         uint32_t a0, uint32_t a1, uint32_t a2, uint32_t a3,
                                         uint32_t b0, uint32_t b1) {
    asm volatile(
        "mma.sync.aligned.m16n8k8.row.col.f32.tf32.tf32.f32 "
        "{%0,%1,%2,%3}, {%4,%5,%6,%7}, {%8,%9}, {%0,%1,%2,%3};\n"
        : "+f"(d0), "+f"(d1), "+f"(d2), "+f"(d3)
        : "r"(a0), "r"(a1), "r"(a2), "r"(a3), "r"(b0), "r"(b1));
}

// ---- cp.async helpers ----
__device__ __forceinline__ void cpa16(uint32_t saddr, const void* gptr) {
    asm volatile("cp.async.cg.shared.global [%0], [%1], 16;" :: "r"(saddr), "l"(gptr) : "memory");
}
__device__ __forceinline__ void cpa_commit() {
    asm volatile("cp.async.commit_group;" ::: "memory");
}
__device__ __forceinline__ void cpa_wait_all() {
    asm volatile("cp.async.wait_group 0;" ::: "memory");
}

__global__ void __launch_bounds__(NTHREADS, 1)
attn_flash_tf32(const float* __restrict__ q,
                const float* __restrict__ k,
                const float* __restrict__ v,
                float* __restrict__ out)
{
    extern __shared__ float smem[];
    float* Qs   = smem;               // [BM][LDQ] tf32 bits, pre-scaled by 1/sqrt(D)
    float* Ks   = Qs + BM*LDQ;        // [BN][LDK] raw fp32
    float* Vs   = Ks + BN*LDK;        // [BN][LDV] raw fp32
    float* Ps   = Vs + BN*LDV;        // [BM][LDP] scores / probabilities (fp32)
    float* rowm = Ps + BM*LDP;        // running max
    float* rowl = rowm + BM;          // running denom
    float* rowc = rowl + BM;          // per-tile correction factor

    const int tid  = threadIdx.x;
    const int b    = blockIdx.y;
    const int q0   = blockIdx.x * BM;
    const int wid  = tid >> 5;
    const int lane = tid & 31;
    const int lg   = lane >> 2;       // groupID (0..7)
    const int l4   = lane & 3;        // threadID in group (0..3)

    // S-phase warp tiling: 4 m16-tiles x 2 n32-groups over the 64x64 S tile
    const int wm_s = wid & 3;         // rows wm_s*16
    const int wn_s = wid >> 2;        // key cols wn_s*32 (4 n8-tiles)
    // PV-phase warp tiling: 2 m32-groups x 4 d64-groups over the 64x256 O tile
    const int wm_v = wid & 1;         // rows wm_v*32 (two m16-tiles)
    const int wn_v = wid >> 1;        // d cols wn_v*64 (8 n8-tiles)

    const float* gQ = q + ((size_t)b * S_LEN + q0) * HD;
    const float* gK = k + (size_t)b * S_LEN * HD;
    const float* gV = v + (size_t)b * S_LEN * HD;

    const uint32_t sKs = (uint32_t)__cvta_generic_to_shared(Ks);
    const uint32_t sVs = (uint32_t)__cvta_generic_to_shared(Vs);

    // ---- prologue: load Q (scale + round to tf32 once), async-load K(0)/V(0) ----
    #pragma unroll
    for (int it = 0; it < (BM*HD/4)/NTHREADS; ++it) {
        int idx = it * NTHREADS + tid;
        int r = idx >> 6;               // HD/4 = 64 float4 per row
        int c = (idx & 63) << 2;
        float4 val = *(const float4*)(gQ + (size_t)r * HD + c);
        float4 tf;
        tf.x = __uint_as_float(f2tf(val.x * SCALE));
        tf.y = __uint_as_float(f2tf(val.y * SCALE));
        tf.z = __uint_as_float(f2tf(val.z * SCALE));
        tf.w = __uint_as_float(f2tf(val.w * SCALE));
        *(float4*)(Qs + r * LDQ + c) = tf;
    }
    for (int idx = tid; idx < BN*(HD/4); idx += NTHREADS) {
        int r = idx >> 6, c = (idx & 63) << 2;
        cpa16(sKs + (uint32_t)(r * LDK + c) * 4u, gK + (size_t)r * HD + c);
    }
    cpa_commit();
    for (int idx = tid; idx < BN*(HD/4); idx += NTHREADS) {
        int r = idx >> 6, c = (idx & 63) << 2;
        cpa16(sVs + (uint32_t)(r * LDV + c) * 4u, gV + (size_t)r * HD + c);
    }
    cpa_commit();
    if (tid < BM) { rowm[tid] = -1e30f; rowl[tid] = 0.0f; }

    // O accumulators: [m16-tile][n8-tile][4 regs], rows wm_v*32+mi*16+{lg,lg+8},
    // cols wn_v*64 + nt*8 + 2*l4 + {0,1}
    float oacc[2][8][4];
    #pragma unroll
    for (int mi = 0; mi < 2; ++mi)
        #pragma unroll
        for (int nt = 0; nt < 8; ++nt)
            #pragma unroll
            for (int r = 0; r < 4; ++r) oacc[mi][nt][r] = 0.0f;

    for (int t = 0; t < NT; ++t) {
        cpa_wait_all();
        __syncthreads();                      // K(t), V(t) visible to all

        // ---------- phase 1: S = (Q*scale) @ K^T via tf32 mma ----------
        {
            float sacc[4][4];
            #pragma unroll
            for (int nt = 0; nt < 4; ++nt)
                #pragma unroll
                for (int r = 0; r < 4; ++r) sacc[nt][r] = 0.0f;

            const float* qb = Qs + (wm_s * 16) * LDQ;
            #pragma unroll 4
            for (int ks = 0; ks < HD / 8; ++ks) {
                const int k0 = ks * 8;
                // A fragment (Qs already tf32 bits)
                uint32_t a0 = __float_as_uint(qb[(lg    ) * LDQ + k0 + l4    ]);
                uint32_t a1 = __float_as_uint(qb[(lg + 8) * LDQ + k0 + l4    ]);
                uint32_t a2 = __float_as_uint(qb[(lg    ) * LDQ + k0 + l4 + 4]);
                uint32_t a3 = __float_as_uint(qb[(lg + 8) * LDQ + k0 + l4 + 4]);
                #pragma unroll
                for (int nt = 0; nt < 4; ++nt) {
                    const int n0 = wn_s * 32 + nt * 8;
                    uint32_t b0 = f2tf(Ks[(n0 + lg) * LDK + k0 + l4    ]);
                    uint32_t b1 = f2tf(Ks[(n0 + lg) * LDK + k0 + l4 + 4]);
                    mma_tf32(sacc[nt][0], sacc[nt][1], sacc[nt][2], sacc[nt][3],
                             a0, a1, a2, a3, b0, b1);
                }
            }
            // write C fragments to Ps
            const int row = wm_s * 16 + lg;
            #pragma unroll
            for (int nt = 0; nt < 4; ++nt) {
                const int col = wn_s * 32 + nt * 8 + 2 * l4;
                *(float2*)(Ps + row * LDP + col)       = make_float2(sacc[nt][0], sacc[nt][1]);
                *(float2*)(Ps + (row + 8) * LDP + col) = make_float2(sacc[nt][2], sacc[nt][3]);
            }
        }
        __syncthreads();                      // Ps complete; Ks now free

        // prefetch K(t+1) into the freed K buffer (overlaps softmax + PV)
        if (t + 1 < NT) {
            const float* srcK = gK + (size_t)(t + 1) * BN * HD;
            for (int idx = tid; idx < BN*(HD/4); idx += NTHREADS) {
                int r = idx >> 6, c = (idx & 63) << 2;
                cpa16(sKs + (uint32_t)(r * LDK + c) * 4u, srcK + (size_t)r * HD + c);
            }
        }
        cpa_commit();

        // ---------- phase 2: online softmax, 4 lanes per row ----------
        {
            int row = tid >> 2;
            int sub = tid & 3;
            float* prow = Ps + row * LDP + sub * 16;
            float4 x0 = *(float4*)(prow + 0);
            float4 x1 = *(float4*)(prow + 4);
            float4 x2 = *(float4*)(prow + 8);
            float4 x3 = *(float4*)(prow + 12);

            float mloc = fmaxf(fmaxf(fmaxf(x0.x, x0.y), fmaxf(x0.z, x0.w)),
                               fmaxf(fmaxf(x1.x, x1.y), fmaxf(x1.z, x1.w)));
            mloc = fmaxf(mloc, fmaxf(fmaxf(fmaxf(x2.x, x2.y), fmaxf(x2.z, x2.w)),
                                     fmaxf(fmaxf(x3.x, x3.y), fmaxf(x3.z, x3.w))));
            mloc = fmaxf(mloc, __shfl_xor_sync(0xffffffffu, mloc, 1));
            mloc = fmaxf(mloc, __shfl_xor_sync(0xffffffffu, mloc, 2));

            float mold = rowm[row];
            float mnew = fmaxf(mold, mloc);

            x0.x = __expf(x0.x - mnew); x0.y = __expf(x0.y - mnew);
            x0.z = __expf(x0.z - mnew); x0.w = __expf(x0.w - mnew);
            x1.x = __expf(x1.x - mnew); x1.y = __expf(x1.y - mnew);
            x1.z = __expf(x1.z - mnew); x1.w = __expf(x1.w - mnew);
            x2.x = __expf(x2.x - mnew); x2.y = __expf(x2.y - mnew);
            x2.z = __expf(x2.z - mnew); x2.w = __expf(x2.w - mnew);
            x3.x = __expf(x3.x - mnew); x3.y = __expf(x3.y - mnew);
            x3.z = __expf(x3.z - mnew); x3.w = __expf(x3.w - mnew);

            float ssum = (x0.x + x0.y + x0.z + x0.w) + (x1.x + x1.y + x1.z + x1.w)
                       + (x2.x + x2.y + x2.z + x2.w) + (x3.x + x3.y + x3.z + x3.w);

            *(float4*)(prow + 0)  = x0;
            *(float4*)(prow + 4)  = x1;
            *(float4*)(prow + 8)  = x2;
            *(float4*)(prow + 12) = x3;

            ssum += __shfl_xor_sync(0xffffffffu, ssum, 1);
            ssum += __shfl_xor_sync(0xffffffffu, ssum, 2);

            if (sub == 0) {
                float corr = __expf(mold - mnew);   // first tile: exp(-inf) -> 0
                rowc[row] = corr;
                rowm[row] = mnew;
                rowl[row] = rowl[row] * corr + ssum;
            }
        }
        __syncthreads();                      // P, rowc stable

        // ---------- phase 3: O = O*corr + P @ V via tf32 mma ----------
        {
            #pragma unroll
            for (int mi = 0; mi < 2; ++mi) {
                const int rbase = wm_v * 32 + mi * 16;
                float clo = rowc[rbase + lg];
                float chi = rowc[rbase + 8 + lg];
                #pragma unroll
                for (int nt = 0; nt < 8; ++nt) {
                    oacc[mi][nt][0] *= clo; oacc[mi][nt][1] *= clo;
                    oacc[mi][nt][2] *= chi; oacc[mi][nt][3] *= chi;
                }
            }
            #pragma unroll 2
            for (int ks = 0; ks < BN / 8; ++ks) {
                const int k0 = ks * 8;
                // B fragments: V[key][d] as col-major KxN
                uint32_t bf[8][2];
                #pragma unroll
                for (int nt = 0; nt < 8; ++nt) {
                    const int d0 = wn_v * 64 + nt * 8 + lg;
                    bf[nt][0] = f2tf(Vs[(k0 + l4    ) * LDV + d0]);
                    bf[nt][1] = f2tf(Vs[(k0 + l4 + 4) * LDV + d0]);
                }
                #pragma unroll
                for (int mi = 0; mi < 2; ++mi) {
                    const int rbase = wm_v * 32 + mi * 16;
                    uint32_t a0 = f2tf(Ps[(rbase + lg    ) * LDP + k0 + l4    ]);
                    uint32_t a1 = f2tf(Ps[(rbase + 8 + lg) * LDP + k0 + l4    ]);
                    uint32_t a2 = f2tf(Ps[(rbase + lg    ) * LDP + k0 + l4 + 4]);
                    uint32_t a3 = f2tf(Ps[(rbase + 8 + lg) * LDP + k0 + l4 + 4]);
                    #pragma unroll
                    for (int nt = 0; nt < 8; ++nt)
                        mma_tf32(oacc[mi][nt][0], oacc[mi][nt][1],
                                 oacc[mi][nt][2], oacc[mi][nt][3],
                                 a0, a1, a2, a3, bf[nt][0], bf[nt][1]);
                }
            }
        }
        __syncthreads();                      // Vs now free

        // prefetch V(t+1)
        if (t + 1 < NT) {
            const float* srcV = gV + (size_t)(t + 1) * BN * HD;
            for (int idx = tid; idx < BN*(HD/4); idx += NTHREADS) {
                int r = idx >> 6, c = (idx & 63) << 2;
                cpa16(sVs + (uint32_t)(r * LDV + c) * 4u, srcV + (size_t)r * HD + c);
            }
        }
        cpa_commit();
    }

    // ---- epilogue: normalize by running denom, store ----
    #pragma unroll
    for (int mi = 0; mi < 2; ++mi) {
        #pragma unroll
        for (int half = 0; half < 2; ++half) {
            const int row = wm_v * 32 + mi * 16 + half * 8 + lg;
            const float inv = __fdividef(1.0f, rowl[row]);
            float* dst = out + ((size_t)b * S_LEN + (q0 + row)) * HD + wn_v * 64;
            #pragma unroll
            for (int nt = 0; nt < 8; ++nt) {
                const int c = nt * 8 + 2 * l4;
                float v0 = oacc[mi][nt][2 * half]     * inv;
                float v1 = oacc[mi][nt][2 * half + 1] * inv;
                *(float2*)(dst + c) = make_float2(v0, v1);
            }
        }
    }
}

extern "C" void kernel_launch(void* const* d_in, const int* in_sizes, int n_in,
                              void* d_out, int out_size) {
    const float* q = (const float*)d_in[0];
    const float* k = (const float*)d_in[1];
    const float* v = (const float*)d_in[2];
    float* out = (float*)d_out;

    const int B = in_sizes[0] / (S_LEN * HD);

    cudaFuncSetAttribute(attn_flash_tf32,
                         cudaFuncAttributeMaxDynamicSharedMemorySize, SMEM_BYTES);

    dim3 grid(S_LEN / BM, B);
    attn_flash_tf32<<<grid, NTHREADS, SMEM_BYTES>>>(q, k, v, out);
}